// round 12
// baseline (speedup 1.0000x reference)
#include <cuda_runtime.h>
#include <cuda_bf16.h>
#include <cuda_fp16.h>
#include <mma.h>
#include <stdint.h>

using namespace nvcuda;

#define NN 100000
#define EE 1600000
#define FN 32
#define FE 8
#define HH 64
#define NB_SCAN 391   // ceil(NN/256)

// ---------------- scratch (device globals) ------------------------------------
__device__ __half g_g[NN * HH];   // fp16 node rows (embed out / gathered by gmid)
__device__ __half g_g2[NN * HH];  // fp16 node rows (gmid out / gathered by gfinal)
__device__ __half g_a[NN * HH];   // fp16: h2 @ W_p1[0:64]
__device__ __half g_b[NN * HH];   // fp16: h2 @ W_p1[64:128]
__device__ float  g_dinv[NN];
__device__ int    g_degi[NN];
__device__ int    g_off[NN];
__device__ int    g_offtmp[NN];
__device__ int    g_cur[NN];
__device__ int    g_bsum[512];
__device__ int    g_csr[EE];

// ---------------- degree / norm / CSR build -----------------------------------
__global__ void k_zero() {
    int n = blockIdx.x * blockDim.x + threadIdx.x;
    if (n < NN) g_degi[n] = 0;
}

__global__ void k_deg(const int* __restrict__ ei) {
    int e = blockIdx.x * blockDim.x + threadIdx.x;
    if (e < EE) atomicAdd(&g_degi[__ldg(&ei[EE + e])], 1);
}

__global__ void k_scanA() {
    __shared__ int sm[256];
    int t = threadIdx.x;
    int idx = blockIdx.x * 256 + t;
    int v = (idx < NN) ? g_degi[idx] : 0;
    sm[t] = v;
    __syncthreads();
#pragma unroll
    for (int o = 1; o < 256; o <<= 1) {
        int x = (t >= o) ? sm[t - o] : 0;
        __syncthreads();
        sm[t] += x;
        __syncthreads();
    }
    if (idx < NN) g_offtmp[idx] = sm[t] - v;
    if (t == 255) g_bsum[blockIdx.x] = sm[255];
}

__global__ void k_scanC() {
    __shared__ int sm[256];
    int t = threadIdx.x;
    int bid = blockIdx.x;
    int v = 0;
    if (t < bid) v += g_bsum[t];
    if (t + 256 < bid) v += g_bsum[t + 256];
    sm[t] = v;
    __syncthreads();
#pragma unroll
    for (int o = 128; o > 0; o >>= 1) {
        if (t < o) sm[t] += sm[t + o];
        __syncthreads();
    }
    int bbase = sm[0];
    int idx = bid * 256 + t;
    if (idx < NN) {
        int o = g_offtmp[idx] + bbase;
        g_off[idx] = o;
        g_cur[idx] = o;
        g_dinv[idx] = rsqrtf((float)(g_degi[idx] + 1));
    }
}

__global__ void k_fill(const int* __restrict__ ei) {
    int e = blockIdx.x * blockDim.x + threadIdx.x;
    if (e < EE) {
        int d = __ldg(&ei[EE + e]);
        int pos = atomicAdd(&g_cur[d], 1);
        g_csr[pos] = __ldg(&ei[e]);
    }
}

// ================== shared helpers =============================================
#define LDH 72    // fp16 ldm for 64-wide tiles
#define LDX 40    // fp16 ldm for 32-wide x tile
#define LDC 72    // fp32 ldm for 64-wide C buffer
#define LDW 136   // fp16 ldm for 128-wide combined Wp1 tile
#define LDC2 136  // fp32 ldm for 128-wide C buffer

// gather one node's fp32 accumulator slice (4 cols at p) from fp16 table
__device__ __forceinline__ float4 gather_node(const __half* __restrict__ tab,
                                              int n, int p, unsigned hm) {
    uint2 selfraw = *reinterpret_cast<const uint2*>(&tab[(long)n * HH + p * 4]);
    float2 lo = __half22float2(*reinterpret_cast<const __half2*>(&selfraw.x));
    float2 hi = __half22float2(*reinterpret_cast<const __half2*>(&selfraw.y));
    float4 acc = make_float4(lo.x, lo.y, hi.x, hi.y);

    const int beg = g_off[n];
    const int end = beg + g_degi[n];
    for (int b = beg; b < end; b += 16) {
        int rem = end - b;
        int cnt = rem < 16 ? rem : 16;
        int myi = (p < cnt) ? __ldg(&g_csr[b + p]) : 0;
        for (int k = 0; k < cnt; k++) {
            int s = __shfl_sync(hm, myi, k, 16);
            uint2 raw = __ldg(reinterpret_cast<const uint2*>(&tab[(long)s * HH]) + p);
            float2 l2 = __half22float2(*reinterpret_cast<const __half2*>(&raw.x));
            float2 h2 = __half22float2(*reinterpret_cast<const __half2*>(&raw.y));
            acc.x += l2.x; acc.y += l2.y; acc.z += h2.x; acc.w += h2.y;
        }
    }
    return acc;
}

__device__ __forceinline__ uint2 relu_pack(float4 v, float4 bb, float di) {
    __half2 lo = __floats2half2_rn(fmaxf(fmaf(v.x, di, bb.x), 0.f),
                                   fmaxf(fmaf(v.y, di, bb.y), 0.f));
    __half2 hi = __floats2half2_rn(fmaxf(fmaf(v.z, di, bb.z), 0.f),
                                   fmaxf(fmaf(v.w, di, bb.w), 0.f));
    uint2 r;
    r.x = *reinterpret_cast<unsigned*>(&lo);
    r.y = *reinterpret_cast<unsigned*>(&hi);
    return r;
}

// ---------------- K1: h0 = relu(x@We+be); g1' = (h0@Wc1)*dinv ----------------
__global__ __launch_bounds__(256) void k_embed(const float* __restrict__ x,
                                               const float* __restrict__ We,
                                               const float* __restrict__ be,
                                               const float* __restrict__ Wc1) {
    const int tid = threadIdx.x;
    const int warp = tid >> 5;
    const int base = blockIdx.x * 32;

    __shared__ __align__(16) __half xh[32 * LDX];
    __shared__ __align__(16) __half weh[FN * LDH];
    __shared__ __align__(16) __half wch[HH * LDH];
    __shared__ __align__(16) __half hh[32 * LDH];
    __shared__ __align__(16) float  cbuf[32 * LDC];

    for (int i = tid; i < 32 * FN; i += 256)
        xh[(i >> 5) * LDX + (i & 31)] = __float2half(x[(long)base * FN + i]);
    for (int i = tid; i < FN * HH; i += 256)
        weh[(i >> 6) * LDH + (i & 63)] = __float2half(We[i]);
    for (int i = tid; i < HH * HH; i += 256)
        wch[(i >> 6) * LDH + (i & 63)] = __float2half(Wc1[i]);
    __syncthreads();

    const int wm = warp >> 2;
    const int wn = warp & 3;

    {
        wmma::fragment<wmma::accumulator, 16, 16, 16, float> cf;
        wmma::fill_fragment(cf, 0.0f);
#pragma unroll
        for (int kk = 0; kk < FN / 16; kk++) {
            wmma::fragment<wmma::matrix_a, 16, 16, 16, __half, wmma::row_major> af;
            wmma::fragment<wmma::matrix_b, 16, 16, 16, __half, wmma::row_major> bf;
            wmma::load_matrix_sync(af, xh + wm * 16 * LDX + kk * 16, LDX);
            wmma::load_matrix_sync(bf, weh + kk * 16 * LDH + wn * 16, LDH);
            wmma::mma_sync(cf, af, bf, cf);
        }
        wmma::store_matrix_sync(cbuf + wm * 16 * LDC + wn * 16, cf, LDC,
                                wmma::mem_row_major);
    }
    __syncthreads();

    for (int i = tid; i < 32 * HH; i += 256) {
        int r = i >> 6, c = i & 63;
        hh[r * LDH + c] = __float2half(fmaxf(cbuf[r * LDC + c] + __ldg(&be[c]), 0.f));
    }
    __syncthreads();

    {
        wmma::fragment<wmma::accumulator, 16, 16, 16, float> cf;
        wmma::fill_fragment(cf, 0.0f);
#pragma unroll
        for (int kk = 0; kk < HH / 16; kk++) {
            wmma::fragment<wmma::matrix_a, 16, 16, 16, __half, wmma::row_major> af;
            wmma::fragment<wmma::matrix_b, 16, 16, 16, __half, wmma::row_major> bf;
            wmma::load_matrix_sync(af, hh + wm * 16 * LDH + kk * 16, LDH);
            wmma::load_matrix_sync(bf, wch + kk * 16 * LDH + wn * 16, LDH);
            wmma::mma_sync(cf, af, bf, cf);
        }
        wmma::store_matrix_sync(cbuf + wm * 16 * LDC + wn * 16, cf, LDC,
                                wmma::mem_row_major);
    }
    __syncthreads();

    for (int i = tid; i < 32 * (HH / 2); i += 256) {
        int r = i >> 5, c2 = (i & 31) * 2;
        float di = g_dinv[base + r];
        __half2 hv = __floats2half2_rn(cbuf[r * LDC + c2] * di,
                                       cbuf[r * LDC + c2 + 1] * di);
        *reinterpret_cast<__half2*>(&g_g[(long)(base + r) * HH + c2]) = hv;
    }
}

// ---------------- K2: fused gather(g_g) + conv2 GEMM -> g_g2 ------------------
__global__ __launch_bounds__(256) void k_gmid(const float* __restrict__ bc,
                                              const float* __restrict__ Wc) {
    const int tid = threadIdx.x;
    const int warp = tid >> 5;
    const int base = blockIdx.x * 32;
    const int p = tid & 15;
    const int grp = tid >> 4;
    const unsigned hm = 0xFFFFu << (tid & 16);

    __shared__ __align__(16) __half wch[HH * LDH];
    __shared__ __align__(16) __half hh[32 * LDH];
    __shared__ __align__(16) float  cbuf[32 * LDC];

    for (int i = tid; i < HH * HH; i += 256)
        wch[(i >> 6) * LDH + (i & 63)] = __float2half(Wc[i]);

    // gather: 16 groups x 2 nodes
    float4 bb = __ldg(reinterpret_cast<const float4*>(bc) + p);
#pragma unroll
    for (int rep = 0; rep < 2; rep++) {
        int r = grp * 2 + rep;
        int n = base + r;
        float4 acc = gather_node(g_g, n, p, hm);
        *reinterpret_cast<uint2*>(&hh[r * LDH + p * 4]) =
            relu_pack(acc, bb, g_dinv[n]);
    }
    __syncthreads();

    const int wm = warp >> 2;
    const int wn = warp & 3;
    {
        wmma::fragment<wmma::accumulator, 16, 16, 16, float> cf;
        wmma::fill_fragment(cf, 0.0f);
#pragma unroll
        for (int kk = 0; kk < HH / 16; kk++) {
            wmma::fragment<wmma::matrix_a, 16, 16, 16, __half, wmma::row_major> af;
            wmma::fragment<wmma::matrix_b, 16, 16, 16, __half, wmma::row_major> bf;
            wmma::load_matrix_sync(af, hh + wm * 16 * LDH + kk * 16, LDH);
            wmma::load_matrix_sync(bf, wch + kk * 16 * LDH + wn * 16, LDH);
            wmma::mma_sync(cf, af, bf, cf);
        }
        wmma::store_matrix_sync(cbuf + wm * 16 * LDC + wn * 16, cf, LDC,
                                wmma::mem_row_major);
    }
    __syncthreads();

    for (int i = tid; i < 32 * (HH / 2); i += 256) {
        int r = i >> 5, c2 = (i & 31) * 2;
        float di = g_dinv[base + r];
        __half2 hv = __floats2half2_rn(cbuf[r * LDC + c2] * di,
                                       cbuf[r * LDC + c2 + 1] * di);
        *reinterpret_cast<__half2*>(&g_g2[(long)(base + r) * HH + c2]) = hv;
    }
}

// ---------------- K3: fused gather(g_g2) + [a|b] GEMM -> g_a, g_b -------------
__global__ __launch_bounds__(256) void k_gfinal(const float* __restrict__ bc2,
                                                const float* __restrict__ Wp1) {
    const int tid = threadIdx.x;
    const int warp = tid >> 5;
    const int base = blockIdx.x * 32;
    const int p = tid & 15;
    const int grp = tid >> 4;
    const unsigned hm = 0xFFFFu << (tid & 16);

    __shared__ __align__(16) __half wab[HH * LDW];
    __shared__ __align__(16) __half hh[32 * LDH];
    __shared__ __align__(16) float  cbuf[32 * LDC2];

    for (int i = tid; i < HH * HH; i += 256) {
        int r = i >> 6, c = i & 63;
        wab[r * LDW + c] = __float2half(Wp1[r * HH + c]);
        wab[r * LDW + 64 + c] = __float2half(Wp1[(HH + r) * HH + c]);
    }

    float4 bb = __ldg(reinterpret_cast<const float4*>(bc2) + p);
#pragma unroll
    for (int rep = 0; rep < 2; rep++) {
        int r = grp * 2 + rep;
        int n = base + r;
        float4 acc = gather_node(g_g2, n, p, hm);
        *reinterpret_cast<uint2*>(&hh[r * LDH + p * 4]) =
            relu_pack(acc, bb, g_dinv[n]);
    }
    __syncthreads();

    const int wm = warp >> 2;
    const int wn = warp & 3;
    {
        wmma::fragment<wmma::accumulator, 16, 16, 16, float> c0, c1;
        wmma::fill_fragment(c0, 0.0f);
        wmma::fill_fragment(c1, 0.0f);
#pragma unroll
        for (int kk = 0; kk < HH / 16; kk++) {
            wmma::fragment<wmma::matrix_a, 16, 16, 16, __half, wmma::row_major> af;
            wmma::fragment<wmma::matrix_b, 16, 16, 16, __half, wmma::row_major> b0, b1;
            wmma::load_matrix_sync(af, hh + wm * 16 * LDH + kk * 16, LDH);
            wmma::load_matrix_sync(b0, wab + kk * 16 * LDW + wn * 16, LDW);
            wmma::load_matrix_sync(b1, wab + kk * 16 * LDW + (wn + 4) * 16, LDW);
            wmma::mma_sync(c0, af, b0, c0);
            wmma::mma_sync(c1, af, b1, c1);
        }
        wmma::store_matrix_sync(cbuf + wm * 16 * LDC2 + wn * 16, c0, LDC2,
                                wmma::mem_row_major);
        wmma::store_matrix_sync(cbuf + wm * 16 * LDC2 + (wn + 4) * 16, c1, LDC2,
                                wmma::mem_row_major);
    }
    __syncthreads();

    for (int i = tid; i < 32 * 64; i += 256) {
        int r = i >> 6, c2 = (i & 63) * 2;
        __half2 hv = __floats2half2_rn(cbuf[r * LDC2 + c2], cbuf[r * LDC2 + c2 + 1]);
        if (c2 < 64)
            *reinterpret_cast<__half2*>(&g_a[(long)(base + r) * HH + c2]) = hv;
        else
            *reinterpret_cast<__half2*>(&g_b[(long)(base + r) * HH + (c2 - 64)]) = hv;
    }
}

// ---------------- K4: per-edge output, 4 edges per 16-thread group -----------
#define EPT 4
__global__ __launch_bounds__(256) void k_edge_out(const int* __restrict__ ei,
                           const float* __restrict__ eattr,
                           const float* __restrict__ Wp1,
                           const float* __restrict__ bp1,
                           const float* __restrict__ wp2,
                           const float* __restrict__ bp2,
                           float* __restrict__ out) {
    const int tid = threadIdx.x;
    const int p = tid & 15;
    const int grp = tid >> 4;
    const int j0 = p * 4;
    long e0 = ((long)blockIdx.x * 16 + grp) * EPT;

    float4 wt[FE];
#pragma unroll
    for (int k = 0; k < FE; k++)
        wt[k] = __ldg(reinterpret_cast<const float4*>(&Wp1[(2 * HH + k) * HH + j0]));
    float4 c0 = __ldg(reinterpret_cast<const float4*>(bp1) + p);
    float4 w2 = __ldg(reinterpret_cast<const float4*>(wp2) + p);
    float bias2 = __ldg(bp2);

    float res[EPT];
#pragma unroll
    for (int t = 0; t < EPT; t++) {
        long e = e0 + t;
        int s = __ldg(&ei[e]);
        int d = __ldg(&ei[EE + e]);
        float eav = (p < FE) ? __ldg(&eattr[e * FE + p]) : 0.0f;

        uint2 ar = __ldg(reinterpret_cast<const uint2*>(&g_a[(long)s * HH]) + p);
        uint2 br = __ldg(reinterpret_cast<const uint2*>(&g_b[(long)d * HH]) + p);
        float2 al = __half22float2(*reinterpret_cast<__half2*>(&ar.x));
        float2 ah = __half22float2(*reinterpret_cast<__half2*>(&ar.y));
        float2 bl = __half22float2(*reinterpret_cast<__half2*>(&br.x));
        float2 bh = __half22float2(*reinterpret_cast<__half2*>(&br.y));

        float4 c = c0;
#pragma unroll
        for (int k = 0; k < FE; k++) {
            float ek = __shfl_sync(0xffffffffu, eav, k, 16);
            c.x = fmaf(ek, wt[k].x, c.x);
            c.y = fmaf(ek, wt[k].y, c.y);
            c.z = fmaf(ek, wt[k].z, c.z);
            c.w = fmaf(ek, wt[k].w, c.w);
        }

        float4 z;
        z.x = fmaxf(al.x + bl.x + c.x, 0.0f);
        z.y = fmaxf(al.y + bl.y + c.y, 0.0f);
        z.z = fmaxf(ah.x + bh.x + c.z, 0.0f);
        z.w = fmaxf(ah.y + bh.y + c.w, 0.0f);

        float part = z.x * w2.x + z.y * w2.y + z.z * w2.z + z.w * w2.w;
#pragma unroll
        for (int off = 8; off >= 1; off >>= 1)
            part += __shfl_down_sync(0xffffffffu, part, off, 16);

        res[t] = part + bias2;
    }
    if (p == 0)
        *reinterpret_cast<float4*>(&out[e0]) =
            make_float4(res[0], res[1], res[2], res[3]);
}

// ---------------- host launcher ----------------------------------------------
extern "C" void kernel_launch(void* const* d_in, const int* in_sizes, int n_in,
                              void* d_out, int out_size) {
    const float* x     = (const float*)d_in[0];
    const float* eattr = (const float*)d_in[1];
    const float* We    = (const float*)d_in[2];
    const float* be    = (const float*)d_in[3];
    const float* Wc1   = (const float*)d_in[4];
    const float* bc1   = (const float*)d_in[5];
    const float* Wc2   = (const float*)d_in[6];
    const float* bc2   = (const float*)d_in[7];
    const float* Wp1   = (const float*)d_in[8];
    const float* bp1   = (const float*)d_in[9];
    const float* wp2   = (const float*)d_in[10];
    const float* bp2   = (const float*)d_in[11];
    const int*   ei    = (const int*)d_in[12];
    float* out = (float*)d_out;

    // CSR build prologue
    k_zero<<<(NN + 255) / 256, 256>>>();
    k_deg<<<(EE + 255) / 256, 256>>>(ei);
    k_scanA<<<NB_SCAN, 256>>>();
    k_scanC<<<NB_SCAN, 256>>>();

    int ngrid = NN / 32;           // 3125

    // fork: k_fill runs concurrently with k_embed
    cudaStream_t s2;
    cudaStreamCreate(&s2);
    cudaEvent_t evFork, evJoin;
    cudaEventCreateWithFlags(&evFork, cudaEventDisableTiming);
    cudaEventCreateWithFlags(&evJoin, cudaEventDisableTiming);

    cudaEventRecord(evFork, 0);
    cudaStreamWaitEvent(s2, evFork, 0);
    k_fill<<<(EE + 255) / 256, 256, 0, s2>>>(ei);
    cudaEventRecord(evJoin, s2);

    k_embed<<<ngrid, 256>>>(x, We, be, Wc1);

    cudaStreamWaitEvent(0, evJoin, 0);

    k_gmid<<<ngrid, 256>>>(bc1, Wc2);
    k_gfinal<<<ngrid, 256>>>(bc2, Wp1);

    k_edge_out<<<EE / (16 * EPT), 256>>>(ei, eattr, Wp1, bp1, wp2, bp2, out);

    cudaEventDestroy(evFork);
    cudaEventDestroy(evJoin);
    cudaStreamDestroy(s2);
}

// round 13
// speedup vs baseline: 1.0002x; 1.0002x over previous
#include <cuda_runtime.h>
#include <cuda_bf16.h>
#include <cuda_fp16.h>
#include <mma.h>
#include <stdint.h>

using namespace nvcuda;

#define NN 100000
#define EE 1600000
#define FN 32
#define FE 8
#define HH 64
#define NB_SCAN 391   // ceil(NN/256)

// ---------------- scratch (device globals) ------------------------------------
__device__ __half g_g[NN * HH];   // fp16: g' = (h@W) * dinv
__device__ float  g_acc[NN * HH]; // fp32 aggregation target
__device__ __half g_a[NN * HH];   // fp16: h2 @ W_p1[0:64]
__device__ __half g_b[NN * HH];   // fp16: h2 @ W_p1[64:128]
__device__ float  g_dinv[NN];
__device__ int    g_degi[NN];
__device__ int    g_off[NN];
__device__ int    g_offtmp[NN];
__device__ int    g_cur[NN];
__device__ int    g_bsum[512];
__device__ int    g_csr[EE];

// ---------------- degree / norm / CSR build -----------------------------------
__global__ void k_zero() {
    int n = blockIdx.x * blockDim.x + threadIdx.x;
    if (n < NN) g_degi[n] = 0;
}

__global__ void k_deg(const int* __restrict__ ei) {
    int e = blockIdx.x * blockDim.x + threadIdx.x;
    if (e < EE) atomicAdd(&g_degi[__ldg(&ei[EE + e])], 1);
}

// dinv only — unblocks k_embed early
__global__ void k_dinv() {
    int n = blockIdx.x * blockDim.x + threadIdx.x;
    if (n < NN) g_dinv[n] = rsqrtf((float)(g_degi[n] + 1));  // +1 self loop
}

__global__ void k_scanA() {
    __shared__ int sm[256];
    int t = threadIdx.x;
    int idx = blockIdx.x * 256 + t;
    int v = (idx < NN) ? g_degi[idx] : 0;
    sm[t] = v;
    __syncthreads();
#pragma unroll
    for (int o = 1; o < 256; o <<= 1) {
        int x = (t >= o) ? sm[t - o] : 0;
        __syncthreads();
        sm[t] += x;
        __syncthreads();
    }
    if (idx < NN) g_offtmp[idx] = sm[t] - v;
    if (t == 255) g_bsum[blockIdx.x] = sm[255];
}

// offsets + fill cursor only (dinv moved to k_dinv)
__global__ void k_scanC() {
    __shared__ int sm[256];
    int t = threadIdx.x;
    int bid = blockIdx.x;
    int v = 0;
    if (t < bid) v += g_bsum[t];
    if (t + 256 < bid) v += g_bsum[t + 256];
    sm[t] = v;
    __syncthreads();
#pragma unroll
    for (int o = 128; o > 0; o >>= 1) {
        if (t < o) sm[t] += sm[t + o];
        __syncthreads();
    }
    int bbase = sm[0];
    int idx = bid * 256 + t;
    if (idx < NN) {
        int o = g_offtmp[idx] + bbase;
        g_off[idx] = o;
        g_cur[idx] = o;
    }
}

__global__ void k_fill(const int* __restrict__ ei) {
    int e = blockIdx.x * blockDim.x + threadIdx.x;
    if (e < EE) {
        int d = __ldg(&ei[EE + e]);
        int pos = atomicAdd(&g_cur[d], 1);
        g_csr[pos] = __ldg(&ei[e]);
    }
}

// ================== node GEMM kernels: 256 threads, 32 nodes/block, HMMA =====
#define LDH 72
#define LDX 40
#define LDC 72
#define LDW 136
#define LDC2 136

// ---------------- K1: h0 = relu(x@We+be); g1' = (h0@Wc1)*dinv ----------------
__global__ __launch_bounds__(256) void k_embed(const float* __restrict__ x,
                                               const float* __restrict__ We,
                                               const float* __restrict__ be,
                                               const float* __restrict__ Wc1) {
    const int tid = threadIdx.x;
    const int warp = tid >> 5;
    const int base = blockIdx.x * 32;

    __shared__ __align__(16) __half xh[32 * LDX];
    __shared__ __align__(16) __half weh[FN * LDH];
    __shared__ __align__(16) __half wch[HH * LDH];
    __shared__ __align__(16) __half hh[32 * LDH];
    __shared__ __align__(16) float  cbuf[32 * LDC];

    for (int i = tid; i < 32 * FN; i += 256)
        xh[(i >> 5) * LDX + (i & 31)] = __float2half(x[(long)base * FN + i]);
    for (int i = tid; i < FN * HH; i += 256)
        weh[(i >> 6) * LDH + (i & 63)] = __float2half(We[i]);
    for (int i = tid; i < HH * HH; i += 256)
        wch[(i >> 6) * LDH + (i & 63)] = __float2half(Wc1[i]);
    __syncthreads();

    const int wm = warp >> 2;
    const int wn = warp & 3;

    {
        wmma::fragment<wmma::accumulator, 16, 16, 16, float> cf;
        wmma::fill_fragment(cf, 0.0f);
#pragma unroll
        for (int kk = 0; kk < FN / 16; kk++) {
            wmma::fragment<wmma::matrix_a, 16, 16, 16, __half, wmma::row_major> af;
            wmma::fragment<wmma::matrix_b, 16, 16, 16, __half, wmma::row_major> bf;
            wmma::load_matrix_sync(af, xh + wm * 16 * LDX + kk * 16, LDX);
            wmma::load_matrix_sync(bf, weh + kk * 16 * LDH + wn * 16, LDH);
            wmma::mma_sync(cf, af, bf, cf);
        }
        wmma::store_matrix_sync(cbuf + wm * 16 * LDC + wn * 16, cf, LDC,
                                wmma::mem_row_major);
    }
    __syncthreads();

    for (int i = tid; i < 32 * HH; i += 256) {
        int r = i >> 6, c = i & 63;
        hh[r * LDH + c] = __float2half(fmaxf(cbuf[r * LDC + c] + __ldg(&be[c]), 0.f));
    }
    __syncthreads();

    {
        wmma::fragment<wmma::accumulator, 16, 16, 16, float> cf;
        wmma::fill_fragment(cf, 0.0f);
#pragma unroll
        for (int kk = 0; kk < HH / 16; kk++) {
            wmma::fragment<wmma::matrix_a, 16, 16, 16, __half, wmma::row_major> af;
            wmma::fragment<wmma::matrix_b, 16, 16, 16, __half, wmma::row_major> bf;
            wmma::load_matrix_sync(af, hh + wm * 16 * LDH + kk * 16, LDH);
            wmma::load_matrix_sync(bf, wch + kk * 16 * LDH + wn * 16, LDH);
            wmma::mma_sync(cf, af, bf, cf);
        }
        wmma::store_matrix_sync(cbuf + wm * 16 * LDC + wn * 16, cf, LDC,
                                wmma::mem_row_major);
    }
    __syncthreads();

    for (int i = tid; i < 32 * (HH / 2); i += 256) {
        int r = i >> 5, c2 = (i & 31) * 2;
        float di = g_dinv[base + r];
        __half2 hv = __floats2half2_rn(cbuf[r * LDC + c2] * di,
                                       cbuf[r * LDC + c2 + 1] * di);
        *reinterpret_cast<__half2*>(&g_g[(long)(base + r) * HH + c2]) = hv;
    }
}

// ---------------- gather-aggregate: acc[n] = g'[n] + sum_{s->n} g'[s] --------
__global__ __launch_bounds__(256) void k_gather() {
    const int tid = threadIdx.x;
    const int p = tid & 15;
    const int grp = tid >> 4;
    const int n = blockIdx.x * 16 + grp;
    const unsigned hm = 0xFFFFu << (tid & 16);

    uint2 selfraw = *reinterpret_cast<const uint2*>(&g_g[(long)n * HH + p * 4]);
    float2 lo = __half22float2(*reinterpret_cast<__half2*>(&selfraw.x));
    float2 hi = __half22float2(*reinterpret_cast<__half2*>(&selfraw.y));
    float4 acc = make_float4(lo.x, lo.y, hi.x, hi.y);

    const int beg = g_off[n];
    const int end = beg + g_degi[n];

    for (int b = beg; b < end; b += 16) {
        int rem = end - b;
        int cnt = rem < 16 ? rem : 16;
        int myi = (p < cnt) ? __ldg(&g_csr[b + p]) : 0;
        for (int k = 0; k < cnt; k++) {
            int s = __shfl_sync(hm, myi, k, 16);
            uint2 raw = __ldg(reinterpret_cast<const uint2*>(&g_g[(long)s * HH]) + p);
            float2 l2 = __half22float2(*reinterpret_cast<__half2*>(&raw.x));
            float2 h2 = __half22float2(*reinterpret_cast<__half2*>(&raw.y));
            acc.x += l2.x; acc.y += l2.y; acc.z += h2.x; acc.w += h2.y;
        }
    }
    *(float4*)&g_acc[(long)n * HH + p * 4] = acc;
}

// ---------------- K3: h1 = relu(acc*dinv + bc); g2' = (h1@Wc2)*dinv ----------
__global__ __launch_bounds__(256) void k_mid(const float* __restrict__ bc,
                                             const float* __restrict__ Wc) {
    const int tid = threadIdx.x;
    const int warp = tid >> 5;
    const int base = blockIdx.x * 32;

    __shared__ __align__(16) __half wch[HH * LDH];
    __shared__ __align__(16) __half hh[32 * LDH];
    __shared__ __align__(16) float  cbuf[32 * LDC];

    for (int i = tid; i < HH * HH; i += 256)
        wch[(i >> 6) * LDH + (i & 63)] = __float2half(Wc[i]);
    for (int i = tid; i < 32 * HH; i += 256) {
        int r = i >> 6, c = i & 63;
        float di = g_dinv[base + r];
        hh[r * LDH + c] = __float2half(
            fmaxf(fmaf(g_acc[(long)(base + r) * HH + c], di, __ldg(&bc[c])), 0.f));
    }
    __syncthreads();

    const int wm = warp >> 2;
    const int wn = warp & 3;
    {
        wmma::fragment<wmma::accumulator, 16, 16, 16, float> cf;
        wmma::fill_fragment(cf, 0.0f);
#pragma unroll
        for (int kk = 0; kk < HH / 16; kk++) {
            wmma::fragment<wmma::matrix_a, 16, 16, 16, __half, wmma::row_major> af;
            wmma::fragment<wmma::matrix_b, 16, 16, 16, __half, wmma::row_major> bf;
            wmma::load_matrix_sync(af, hh + wm * 16 * LDH + kk * 16, LDH);
            wmma::load_matrix_sync(bf, wch + kk * 16 * LDH + wn * 16, LDH);
            wmma::mma_sync(cf, af, bf, cf);
        }
        wmma::store_matrix_sync(cbuf + wm * 16 * LDC + wn * 16, cf, LDC,
                                wmma::mem_row_major);
    }
    __syncthreads();

    for (int i = tid; i < 32 * (HH / 2); i += 256) {
        int r = i >> 5, c2 = (i & 31) * 2;
        float di = g_dinv[base + r];
        __half2 hv = __floats2half2_rn(cbuf[r * LDC + c2] * di,
                                       cbuf[r * LDC + c2 + 1] * di);
        *reinterpret_cast<__half2*>(&g_g[(long)(base + r) * HH + c2]) = hv;
    }
}

// ---------------- K5: h2 = relu(acc*dinv + bc2); [a|b] = h2 @ Wp1' -----------
__global__ __launch_bounds__(256) void k_node_final(const float* __restrict__ bc2,
                                                    const float* __restrict__ Wp1) {
    const int tid = threadIdx.x;
    const int warp = tid >> 5;
    const int base = blockIdx.x * 32;

    __shared__ __align__(16) __half wab[HH * LDW];
    __shared__ __align__(16) __half hh[32 * LDH];
    __shared__ __align__(16) float  cbuf[32 * LDC2];

    for (int i = tid; i < HH * HH; i += 256) {
        int r = i >> 6, c = i & 63;
        wab[r * LDW + c] = __float2half(Wp1[r * HH + c]);
        wab[r * LDW + 64 + c] = __float2half(Wp1[(HH + r) * HH + c]);
    }
    for (int i = tid; i < 32 * HH; i += 256) {
        int r = i >> 6, c = i & 63;
        float di = g_dinv[base + r];
        hh[r * LDH + c] = __float2half(
            fmaxf(fmaf(g_acc[(long)(base + r) * HH + c], di, __ldg(&bc2[c])), 0.f));
    }
    __syncthreads();

    const int wm = warp >> 2;
    const int wn = warp & 3;
    {
        wmma::fragment<wmma::accumulator, 16, 16, 16, float> c0, c1;
        wmma::fill_fragment(c0, 0.0f);
        wmma::fill_fragment(c1, 0.0f);
#pragma unroll
        for (int kk = 0; kk < HH / 16; kk++) {
            wmma::fragment<wmma::matrix_a, 16, 16, 16, __half, wmma::row_major> af;
            wmma::fragment<wmma::matrix_b, 16, 16, 16, __half, wmma::row_major> b0, b1;
            wmma::load_matrix_sync(af, hh + wm * 16 * LDH + kk * 16, LDH);
            wmma::load_matrix_sync(b0, wab + kk * 16 * LDW + wn * 16, LDW);
            wmma::load_matrix_sync(b1, wab + kk * 16 * LDW + (wn + 4) * 16, LDW);
            wmma::mma_sync(c0, af, b0, c0);
            wmma::mma_sync(c1, af, b1, c1);
        }
        wmma::store_matrix_sync(cbuf + wm * 16 * LDC2 + wn * 16, c0, LDC2,
                                wmma::mem_row_major);
        wmma::store_matrix_sync(cbuf + wm * 16 * LDC2 + (wn + 4) * 16, c1, LDC2,
                                wmma::mem_row_major);
    }
    __syncthreads();

    for (int i = tid; i < 32 * 64; i += 256) {
        int r = i >> 6, c2 = (i & 63) * 2;
        __half2 hv = __floats2half2_rn(cbuf[r * LDC2 + c2], cbuf[r * LDC2 + c2 + 1]);
        if (c2 < 64)
            *reinterpret_cast<__half2*>(&g_a[(long)(base + r) * HH + c2]) = hv;
        else
            *reinterpret_cast<__half2*>(&g_b[(long)(base + r) * HH + (c2 - 64)]) = hv;
    }
}

// ---------------- K6: per-edge output, 4 edges per 16-thread group -----------
#define EPT 4
__global__ __launch_bounds__(256) void k_edge_out(const int* __restrict__ ei,
                           const float* __restrict__ eattr,
                           const float* __restrict__ Wp1,
                           const float* __restrict__ bp1,
                           const float* __restrict__ wp2,
                           const float* __restrict__ bp2,
                           float* __restrict__ out) {
    const int tid = threadIdx.x;
    const int p = tid & 15;
    const int grp = tid >> 4;
    const int j0 = p * 4;
    long e0 = ((long)blockIdx.x * 16 + grp) * EPT;

    float4 wt[FE];
#pragma unroll
    for (int k = 0; k < FE; k++)
        wt[k] = __ldg(reinterpret_cast<const float4*>(&Wp1[(2 * HH + k) * HH + j0]));
    float4 c0 = __ldg(reinterpret_cast<const float4*>(bp1) + p);
    float4 w2 = __ldg(reinterpret_cast<const float4*>(wp2) + p);
    float bias2 = __ldg(bp2);

    float res[EPT];
#pragma unroll
    for (int t = 0; t < EPT; t++) {
        long e = e0 + t;
        int s = __ldg(&ei[e]);
        int d = __ldg(&ei[EE + e]);
        float eav = (p < FE) ? __ldg(&eattr[e * FE + p]) : 0.0f;

        uint2 ar = __ldg(reinterpret_cast<const uint2*>(&g_a[(long)s * HH]) + p);
        uint2 br = __ldg(reinterpret_cast<const uint2*>(&g_b[(long)d * HH]) + p);
        float2 al = __half22float2(*reinterpret_cast<__half2*>(&ar.x));
        float2 ah = __half22float2(*reinterpret_cast<__half2*>(&ar.y));
        float2 bl = __half22float2(*reinterpret_cast<__half2*>(&br.x));
        float2 bh = __half22float2(*reinterpret_cast<__half2*>(&br.y));

        float4 c = c0;
#pragma unroll
        for (int k = 0; k < FE; k++) {
            float ek = __shfl_sync(0xffffffffu, eav, k, 16);
            c.x = fmaf(ek, wt[k].x, c.x);
            c.y = fmaf(ek, wt[k].y, c.y);
            c.z = fmaf(ek, wt[k].z, c.z);
            c.w = fmaf(ek, wt[k].w, c.w);
        }

        float4 z;
        z.x = fmaxf(al.x + bl.x + c.x, 0.0f);
        z.y = fmaxf(al.y + bl.y + c.y, 0.0f);
        z.z = fmaxf(ah.x + bh.x + c.z, 0.0f);
        z.w = fmaxf(ah.y + bh.y + c.w, 0.0f);

        float part = z.x * w2.x + z.y * w2.y + z.z * w2.z + z.w * w2.w;
#pragma unroll
        for (int off = 8; off >= 1; off >>= 1)
            part += __shfl_down_sync(0xffffffffu, part, off, 16);

        res[t] = part + bias2;
    }
    if (p == 0)
        *reinterpret_cast<float4*>(&out[e0]) =
            make_float4(res[0], res[1], res[2], res[3]);
}

// ---------------- host launcher ----------------------------------------------
extern "C" void kernel_launch(void* const* d_in, const int* in_sizes, int n_in,
                              void* d_out, int out_size) {
    const float* x     = (const float*)d_in[0];
    const float* eattr = (const float*)d_in[1];
    const float* We    = (const float*)d_in[2];
    const float* be    = (const float*)d_in[3];
    const float* Wc1   = (const float*)d_in[4];
    const float* bc1   = (const float*)d_in[5];
    const float* Wc2   = (const float*)d_in[6];
    const float* bc2   = (const float*)d_in[7];
    const float* Wp1   = (const float*)d_in[8];
    const float* bp1   = (const float*)d_in[9];
    const float* wp2   = (const float*)d_in[10];
    const float* bp2   = (const float*)d_in[11];
    const int*   ei    = (const int*)d_in[12];
    float* out = (float*)d_out;

    int ngrid = NN / 32;           // 3125
    int ggrid = NN / 16;           // 6250

    // degrees + dinv on main stream (k_embed needs only dinv)
    k_zero<<<(NN + 255) / 256, 256>>>();
    k_deg<<<(EE + 255) / 256, 256>>>(ei);
    k_dinv<<<(NN + 255) / 256, 256>>>();

    // fork: scan chain + CSR fill runs concurrently with k_embed
    cudaStream_t s2;
    cudaStreamCreate(&s2);
    cudaEvent_t evFork, evJoin;
    cudaEventCreateWithFlags(&evFork, cudaEventDisableTiming);
    cudaEventCreateWithFlags(&evJoin, cudaEventDisableTiming);

    cudaEventRecord(evFork, 0);
    cudaStreamWaitEvent(s2, evFork, 0);
    k_scanA<<<NB_SCAN, 256, 0, s2>>>();
    k_scanC<<<NB_SCAN, 256, 0, s2>>>();
    k_fill<<<(EE + 255) / 256, 256, 0, s2>>>(ei);
    cudaEventRecord(evJoin, s2);

    k_embed<<<ngrid, 256>>>(x, We, be, Wc1);   // main stream, concurrent

    cudaStreamWaitEvent(0, evJoin, 0);         // join before gather needs CSR

    k_gather<<<ggrid, 256>>>();
    k_mid<<<ngrid, 256>>>(bc1, Wc2);
    k_gather<<<ggrid, 256>>>();
    k_node_final<<<ngrid, 256>>>(bc2, Wp1);

    k_edge_out<<<EE / (16 * EPT), 256>>>(ei, eattr, Wp1, bp1, wp2, bp2, out);

    cudaEventDestroy(evFork);
    cudaEventDestroy(evJoin);
    cudaStreamDestroy(s2);
}

// round 14
// speedup vs baseline: 1.0153x; 1.0151x over previous
#include <cuda_runtime.h>
#include <cuda_bf16.h>
#include <cuda_fp16.h>
#include <mma.h>
#include <stdint.h>

using namespace nvcuda;

#define NN 100000
#define EE 1600000
#define FN 32
#define FE 8
#define HH 64
#define NB_SCAN 391   // ceil(NN/256)

// ---------------- scratch (device globals) ------------------------------------
__device__ __half g_g[NN * HH];   // fp16: g' = (h@W) * dinv
__device__ float  g_acc[NN * HH]; // fp32 aggregation target
__device__ __half g_a[NN * HH];   // fp16: h2 @ W_p1[0:64]
__device__ __half g_b[NN * HH];   // fp16: h2 @ W_p1[64:128]
__device__ float  g_dinv[NN];
__device__ int    g_degi[NN];
__device__ int    g_off[NN];
__device__ int    g_offtmp[NN];
__device__ int    g_cur[NN];
__device__ int    g_bsum[512];
__device__ int    g_csr[EE];

// ---------------- degree / norm / CSR build -----------------------------------
__global__ void k_zero() {
    int n = blockIdx.x * blockDim.x + threadIdx.x;
    if (n < NN) g_degi[n] = 0;
}

__global__ void k_deg(const int* __restrict__ ei) {
    int e = blockIdx.x * blockDim.x + threadIdx.x;
    if (e < EE) atomicAdd(&g_degi[__ldg(&ei[EE + e])], 1);
}

__global__ void k_scanA() {
    __shared__ int sm[256];
    int t = threadIdx.x;
    int idx = blockIdx.x * 256 + t;
    int v = (idx < NN) ? g_degi[idx] : 0;
    sm[t] = v;
    __syncthreads();
#pragma unroll
    for (int o = 1; o < 256; o <<= 1) {
        int x = (t >= o) ? sm[t - o] : 0;
        __syncthreads();
        sm[t] += x;
        __syncthreads();
    }
    if (idx < NN) g_offtmp[idx] = sm[t] - v;
    if (t == 255) g_bsum[blockIdx.x] = sm[255];
}

__global__ void k_scanC() {
    __shared__ int sm[256];
    int t = threadIdx.x;
    int bid = blockIdx.x;
    int v = 0;
    if (t < bid) v += g_bsum[t];
    if (t + 256 < bid) v += g_bsum[t + 256];
    sm[t] = v;
    __syncthreads();
#pragma unroll
    for (int o = 128; o > 0; o >>= 1) {
        if (t < o) sm[t] += sm[t + o];
        __syncthreads();
    }
    int bbase = sm[0];
    int idx = bid * 256 + t;
    if (idx < NN) {
        int o = g_offtmp[idx] + bbase;
        g_off[idx] = o;
        g_cur[idx] = o;
        g_dinv[idx] = rsqrtf((float)(g_degi[idx] + 1));
    }
}

__global__ void k_fill(const int* __restrict__ ei) {
    int e = blockIdx.x * blockDim.x + threadIdx.x;
    if (e < EE) {
        int d = __ldg(&ei[EE + e]);
        int pos = atomicAdd(&g_cur[d], 1);
        g_csr[pos] = __ldg(&ei[e]);
    }
}

// ================== node GEMM kernels: 256 threads, 32 nodes/block, HMMA =====
#define LDH 72
#define LDX 40
#define LDC 72
#define LDW 136
#define LDC2 136

// ---------------- K1: h0 = relu(x@We+be); g1' = (h0@Wc1)*dinv ----------------
__global__ __launch_bounds__(256) void k_embed(const float* __restrict__ x,
                                               const float* __restrict__ We,
                                               const float* __restrict__ be,
                                               const float* __restrict__ Wc1) {
    const int tid = threadIdx.x;
    const int warp = tid >> 5;
    const int base = blockIdx.x * 32;

    __shared__ __align__(16) __half xh[32 * LDX];
    __shared__ __align__(16) __half weh[FN * LDH];
    __shared__ __align__(16) __half wch[HH * LDH];
    __shared__ __align__(16) __half hh[32 * LDH];
    __shared__ __align__(16) float  cbuf[32 * LDC];

    for (int i = tid; i < 32 * FN; i += 256)
        xh[(i >> 5) * LDX + (i & 31)] = __float2half(x[(long)base * FN + i]);
    for (int i = tid; i < FN * HH; i += 256)
        weh[(i >> 6) * LDH + (i & 63)] = __float2half(We[i]);
    for (int i = tid; i < HH * HH; i += 256)
        wch[(i >> 6) * LDH + (i & 63)] = __float2half(Wc1[i]);
    __syncthreads();

    const int wm = warp >> 2;
    const int wn = warp & 3;

    {
        wmma::fragment<wmma::accumulator, 16, 16, 16, float> cf;
        wmma::fill_fragment(cf, 0.0f);
#pragma unroll
        for (int kk = 0; kk < FN / 16; kk++) {
            wmma::fragment<wmma::matrix_a, 16, 16, 16, __half, wmma::row_major> af;
            wmma::fragment<wmma::matrix_b, 16, 16, 16, __half, wmma::row_major> bf;
            wmma::load_matrix_sync(af, xh + wm * 16 * LDX + kk * 16, LDX);
            wmma::load_matrix_sync(bf, weh + kk * 16 * LDH + wn * 16, LDH);
            wmma::mma_sync(cf, af, bf, cf);
        }
        wmma::store_matrix_sync(cbuf + wm * 16 * LDC + wn * 16, cf, LDC,
                                wmma::mem_row_major);
    }
    __syncthreads();

    for (int i = tid; i < 32 * HH; i += 256) {
        int r = i >> 6, c = i & 63;
        hh[r * LDH + c] = __float2half(fmaxf(cbuf[r * LDC + c] + __ldg(&be[c]), 0.f));
    }
    __syncthreads();

    {
        wmma::fragment<wmma::accumulator, 16, 16, 16, float> cf;
        wmma::fill_fragment(cf, 0.0f);
#pragma unroll
        for (int kk = 0; kk < HH / 16; kk++) {
            wmma::fragment<wmma::matrix_a, 16, 16, 16, __half, wmma::row_major> af;
            wmma::fragment<wmma::matrix_b, 16, 16, 16, __half, wmma::row_major> bf;
            wmma::load_matrix_sync(af, hh + wm * 16 * LDH + kk * 16, LDH);
            wmma::load_matrix_sync(bf, wch + kk * 16 * LDH + wn * 16, LDH);
            wmma::mma_sync(cf, af, bf, cf);
        }
        wmma::store_matrix_sync(cbuf + wm * 16 * LDC + wn * 16, cf, LDC,
                                wmma::mem_row_major);
    }
    __syncthreads();

    for (int i = tid; i < 32 * (HH / 2); i += 256) {
        int r = i >> 5, c2 = (i & 31) * 2;
        float di = g_dinv[base + r];
        __half2 hv = __floats2half2_rn(cbuf[r * LDC + c2] * di,
                                       cbuf[r * LDC + c2 + 1] * di);
        *reinterpret_cast<__half2*>(&g_g[(long)(base + r) * HH + c2]) = hv;
    }
}

// ---------------- gather-aggregate: acc[n] = g'[n] + sum_{s->n} g'[s] --------
__global__ __launch_bounds__(256) void k_gather() {
    const int tid = threadIdx.x;
    const int p = tid & 15;
    const int grp = tid >> 4;
    const int n = blockIdx.x * 16 + grp;
    const unsigned hm = 0xFFFFu << (tid & 16);

    uint2 selfraw = *reinterpret_cast<const uint2*>(&g_g[(long)n * HH + p * 4]);
    float2 lo = __half22float2(*reinterpret_cast<__half2*>(&selfraw.x));
    float2 hi = __half22float2(*reinterpret_cast<__half2*>(&selfraw.y));
    float4 acc = make_float4(lo.x, lo.y, hi.x, hi.y);

    const int beg = g_off[n];
    const int end = beg + g_degi[n];

    for (int b = beg; b < end; b += 16) {
        int rem = end - b;
        int cnt = rem < 16 ? rem : 16;
        int myi = (p < cnt) ? __ldg(&g_csr[b + p]) : 0;
        for (int k = 0; k < cnt; k++) {
            int s = __shfl_sync(hm, myi, k, 16);
            uint2 raw = __ldg(reinterpret_cast<const uint2*>(&g_g[(long)s * HH]) + p);
            float2 l2 = __half22float2(*reinterpret_cast<__half2*>(&raw.x));
            float2 h2 = __half22float2(*reinterpret_cast<__half2*>(&raw.y));
            acc.x += l2.x; acc.y += l2.y; acc.z += h2.x; acc.w += h2.y;
        }
    }
    *(float4*)&g_acc[(long)n * HH + p * 4] = acc;
}

// ---------------- K3: h1 = relu(acc*dinv + bc); g2' = (h1@Wc2)*dinv ----------
__global__ __launch_bounds__(256) void k_mid(const float* __restrict__ bc,
                                             const float* __restrict__ Wc) {
    const int tid = threadIdx.x;
    const int warp = tid >> 5;
    const int base = blockIdx.x * 32;

    __shared__ __align__(16) __half wch[HH * LDH];
    __shared__ __align__(16) __half hh[32 * LDH];
    __shared__ __align__(16) float  cbuf[32 * LDC];

    for (int i = tid; i < HH * HH; i += 256)
        wch[(i >> 6) * LDH + (i & 63)] = __float2half(Wc[i]);
    for (int i = tid; i < 32 * HH; i += 256) {
        int r = i >> 6, c = i & 63;
        float di = g_dinv[base + r];
        hh[r * LDH + c] = __float2half(
            fmaxf(fmaf(g_acc[(long)(base + r) * HH + c], di, __ldg(&bc[c])), 0.f));
    }
    __syncthreads();

    const int wm = warp >> 2;
    const int wn = warp & 3;
    {
        wmma::fragment<wmma::accumulator, 16, 16, 16, float> cf;
        wmma::fill_fragment(cf, 0.0f);
#pragma unroll
        for (int kk = 0; kk < HH / 16; kk++) {
            wmma::fragment<wmma::matrix_a, 16, 16, 16, __half, wmma::row_major> af;
            wmma::fragment<wmma::matrix_b, 16, 16, 16, __half, wmma::row_major> bf;
            wmma::load_matrix_sync(af, hh + wm * 16 * LDH + kk * 16, LDH);
            wmma::load_matrix_sync(bf, wch + kk * 16 * LDH + wn * 16, LDH);
            wmma::mma_sync(cf, af, bf, cf);
        }
        wmma::store_matrix_sync(cbuf + wm * 16 * LDC + wn * 16, cf, LDC,
                                wmma::mem_row_major);
    }
    __syncthreads();

    for (int i = tid; i < 32 * (HH / 2); i += 256) {
        int r = i >> 5, c2 = (i & 31) * 2;
        float di = g_dinv[base + r];
        __half2 hv = __floats2half2_rn(cbuf[r * LDC + c2] * di,
                                       cbuf[r * LDC + c2 + 1] * di);
        *reinterpret_cast<__half2*>(&g_g[(long)(base + r) * HH + c2]) = hv;
    }
}

// ---------------- K5: h2 = relu(acc*dinv + bc2); [a|b] = h2 @ Wp1' -----------
__global__ __launch_bounds__(256) void k_node_final(const float* __restrict__ bc2,
                                                    const float* __restrict__ Wp1) {
    const int tid = threadIdx.x;
    const int warp = tid >> 5;
    const int base = blockIdx.x * 32;

    __shared__ __align__(16) __half wab[HH * LDW];
    __shared__ __align__(16) __half hh[32 * LDH];
    __shared__ __align__(16) float  cbuf[32 * LDC2];

    for (int i = tid; i < HH * HH; i += 256) {
        int r = i >> 6, c = i & 63;
        wab[r * LDW + c] = __float2half(Wp1[r * HH + c]);
        wab[r * LDW + 64 + c] = __float2half(Wp1[(HH + r) * HH + c]);
    }
    for (int i = tid; i < 32 * HH; i += 256) {
        int r = i >> 6, c = i & 63;
        float di = g_dinv[base + r];
        hh[r * LDH + c] = __float2half(
            fmaxf(fmaf(g_acc[(long)(base + r) * HH + c], di, __ldg(&bc2[c])), 0.f));
    }
    __syncthreads();

    const int wm = warp >> 2;
    const int wn = warp & 3;
    {
        wmma::fragment<wmma::accumulator, 16, 16, 16, float> c0, c1;
        wmma::fill_fragment(c0, 0.0f);
        wmma::fill_fragment(c1, 0.0f);
#pragma unroll
        for (int kk = 0; kk < HH / 16; kk++) {
            wmma::fragment<wmma::matrix_a, 16, 16, 16, __half, wmma::row_major> af;
            wmma::fragment<wmma::matrix_b, 16, 16, 16, __half, wmma::row_major> b0, b1;
            wmma::load_matrix_sync(af, hh + wm * 16 * LDH + kk * 16, LDH);
            wmma::load_matrix_sync(b0, wab + kk * 16 * LDW + wn * 16, LDW);
            wmma::load_matrix_sync(b1, wab + kk * 16 * LDW + (wn + 4) * 16, LDW);
            wmma::mma_sync(c0, af, b0, c0);
            wmma::mma_sync(c1, af, b1, c1);
        }
        wmma::store_matrix_sync(cbuf + wm * 16 * LDC2 + wn * 16, c0, LDC2,
                                wmma::mem_row_major);
        wmma::store_matrix_sync(cbuf + wm * 16 * LDC2 + (wn + 4) * 16, c1, LDC2,
                                wmma::mem_row_major);
    }
    __syncthreads();

    for (int i = tid; i < 32 * 64; i += 256) {
        int r = i >> 6, c2 = (i & 63) * 2;
        __half2 hv = __floats2half2_rn(cbuf[r * LDC2 + c2], cbuf[r * LDC2 + c2 + 1]);
        if (c2 < 64)
            *reinterpret_cast<__half2*>(&g_a[(long)(base + r) * HH + c2]) = hv;
        else
            *reinterpret_cast<__half2*>(&g_b[(long)(base + r) * HH + (c2 - 64)]) = hv;
    }
}

// ---------------- K6: per-edge output; c-loop in packed fma.rn.f32x2 ----------
#define EPT 4
__global__ __launch_bounds__(256) void k_edge_out(const int* __restrict__ ei,
                           const float* __restrict__ eattr,
                           const float* __restrict__ Wp1,
                           const float* __restrict__ bp1,
                           const float* __restrict__ wp2,
                           const float* __restrict__ bp2,
                           float* __restrict__ out) {
    const int tid = threadIdx.x;
    const int p = tid & 15;
    const int grp = tid >> 4;
    const int j0 = p * 4;
    long e0 = ((long)blockIdx.x * 16 + grp) * EPT;

    // Wp1 tail packed as f32x2 pairs (exact fp32)
    unsigned long long wtp[FE][2];
#pragma unroll
    for (int k = 0; k < FE; k++) {
        float4 w = __ldg(reinterpret_cast<const float4*>(&Wp1[(2 * HH + k) * HH + j0]));
        asm("mov.b64 %0, {%1, %2};" : "=l"(wtp[k][0]) : "f"(w.x), "f"(w.y));
        asm("mov.b64 %0, {%1, %2};" : "=l"(wtp[k][1]) : "f"(w.z), "f"(w.w));
    }
    unsigned long long c0p0, c0p1;
    {
        float4 c0 = __ldg(reinterpret_cast<const float4*>(bp1) + p);
        asm("mov.b64 %0, {%1, %2};" : "=l"(c0p0) : "f"(c0.x), "f"(c0.y));
        asm("mov.b64 %0, {%1, %2};" : "=l"(c0p1) : "f"(c0.z), "f"(c0.w));
    }
    float4 w2 = __ldg(reinterpret_cast<const float4*>(wp2) + p);
    float bias2 = __ldg(bp2);

    float res[EPT];
#pragma unroll
    for (int t = 0; t < EPT; t++) {
        long e = e0 + t;
        int s = __ldg(&ei[e]);
        int d = __ldg(&ei[EE + e]);
        float eav = (p < FE) ? __ldg(&eattr[e * FE + p]) : 0.0f;

        uint2 ar = __ldg(reinterpret_cast<const uint2*>(&g_a[(long)s * HH]) + p);
        uint2 br = __ldg(reinterpret_cast<const uint2*>(&g_b[(long)d * HH]) + p);
        float2 al = __half22float2(*reinterpret_cast<__half2*>(&ar.x));
        float2 ah = __half22float2(*reinterpret_cast<__half2*>(&ar.y));
        float2 bl = __half22float2(*reinterpret_cast<__half2*>(&br.x));
        float2 bh = __half22float2(*reinterpret_cast<__half2*>(&br.y));

        unsigned long long cp0 = c0p0, cp1 = c0p1;
#pragma unroll
        for (int k = 0; k < FE; k++) {
            float ek = __shfl_sync(0xffffffffu, eav, k, 16);
            unsigned long long ekp;
            asm("mov.b64 %0, {%1, %1};" : "=l"(ekp) : "f"(ek));
            asm("fma.rn.f32x2 %0, %1, %2, %0;" : "+l"(cp0) : "l"(ekp), "l"(wtp[k][0]));
            asm("fma.rn.f32x2 %0, %1, %2, %0;" : "+l"(cp1) : "l"(ekp), "l"(wtp[k][1]));
        }
        float cx, cy, cz, cw;
        asm("mov.b64 {%0, %1}, %2;" : "=f"(cx), "=f"(cy) : "l"(cp0));
        asm("mov.b64 {%0, %1}, %2;" : "=f"(cz), "=f"(cw) : "l"(cp1));

        float4 z;
        z.x = fmaxf(al.x + bl.x + cx, 0.0f);
        z.y = fmaxf(al.y + bl.y + cy, 0.0f);
        z.z = fmaxf(ah.x + bh.x + cz, 0.0f);
        z.w = fmaxf(ah.y + bh.y + cw, 0.0f);

        float part = z.x * w2.x + z.y * w2.y + z.z * w2.z + z.w * w2.w;
#pragma unroll
        for (int off = 8; off >= 1; off >>= 1)
            part += __shfl_down_sync(0xffffffffu, part, off, 16);

        res[t] = part + bias2;
    }
    if (p == 0)
        *reinterpret_cast<float4*>(&out[e0]) =
            make_float4(res[0], res[1], res[2], res[3]);
}

// ---------------- host launcher (R11 structure — best known) ------------------
extern "C" void kernel_launch(void* const* d_in, const int* in_sizes, int n_in,
                              void* d_out, int out_size) {
    const float* x     = (const float*)d_in[0];
    const float* eattr = (const float*)d_in[1];
    const float* We    = (const float*)d_in[2];
    const float* be    = (const float*)d_in[3];
    const float* Wc1   = (const float*)d_in[4];
    const float* bc1   = (const float*)d_in[5];
    const float* Wc2   = (const float*)d_in[6];
    const float* bc2   = (const float*)d_in[7];
    const float* Wp1   = (const float*)d_in[8];
    const float* bp1   = (const float*)d_in[9];
    const float* wp2   = (const float*)d_in[10];
    const float* bp2   = (const float*)d_in[11];
    const int*   ei    = (const int*)d_in[12];
    float* out = (float*)d_out;

    // CSR build prologue
    k_zero<<<(NN + 255) / 256, 256>>>();
    k_deg<<<(EE + 255) / 256, 256>>>(ei);
    k_scanA<<<NB_SCAN, 256>>>();
    k_scanC<<<NB_SCAN, 256>>>();

    int ngrid = NN / 32;           // 3125
    int ggrid = NN / 16;           // 6250

    // fork: k_fill runs concurrently with k_embed
    cudaStream_t s2;
    cudaStreamCreate(&s2);
    cudaEvent_t evFork, evJoin;
    cudaEventCreateWithFlags(&evFork, cudaEventDisableTiming);
    cudaEventCreateWithFlags(&evJoin, cudaEventDisableTiming);

    cudaEventRecord(evFork, 0);
    cudaStreamWaitEvent(s2, evFork, 0);
    k_fill<<<(EE + 255) / 256, 256, 0, s2>>>(ei);
    cudaEventRecord(evJoin, s2);

    k_embed<<<ngrid, 256>>>(x, We, be, Wc1);

    cudaStreamWaitEvent(0, evJoin, 0);

    k_gather<<<ggrid, 256>>>();
    k_mid<<<ngrid, 256>>>(bc1, Wc2);
    k_gather<<<ggrid, 256>>>();
    k_node_final<<<ngrid, 256>>>(bc2, Wp1);

    k_edge_out<<<EE / (16 * EPT), 256>>>(ei, eattr, Wp1, bp1, wp2, bp2, out);

    cudaEventDestroy(evFork);
    cudaEventDestroy(evJoin);
    cudaStreamDestroy(s2);
}